// round 1
// baseline (speedup 1.0000x reference)
#include <cuda_runtime.h>
#include <cstdint>

#define N_NODES 100000
#define N_EDGES 1000000
#define F 64

// ---------------- scratch (static device globals; no allocation) -------------
__device__ float g_xs [N_NODES * F];   // scaled features
__device__ float g_agg[N_NODES * F];   // aggregation target
__device__ float g_h1 [N_NODES * F];
__device__ float g_h2 [N_NODES * F];
__device__ float g_dego[N_NODES];
__device__ float g_degi[N_NODES];
__device__ float g_invo[N_NODES];
__device__ float g_invi[N_NODES];
__device__ float g_invu[N_NODES];

// ---------------- degree kernels --------------------------------------------
__global__ void k_zero_deg() {
    int i = blockIdx.x * blockDim.x + threadIdx.x;
    if (i < N_NODES) { g_dego[i] = 0.f; g_degi[i] = 0.f; }
}

__global__ void k_degree(const int* __restrict__ src, const int* __restrict__ dst) {
    int e = blockIdx.x * blockDim.x + threadIdx.x;
    if (e < N_EDGES) {
        atomicAdd(&g_dego[src[e]], 1.f);
        atomicAdd(&g_degi[dst[e]], 1.f);
    }
}

__global__ void k_inv() {
    int i = blockIdx.x * blockDim.x + threadIdx.x;
    if (i < N_NODES) {
        float o = g_dego[i], d = g_degi[i];
        g_invo[i] = 1.f / fmaxf(o, 1.f);
        g_invi[i] = 1.f / fmaxf(d, 1.f);
        g_invu[i] = 1.f / fmaxf(o + d, 1.f);
    }
}

// ---------------- scale + zero agg ------------------------------------------
// i ranges over N_NODES*16 float4's.
__global__ void k_scale_zero(const float* __restrict__ in, const float* __restrict__ inv) {
    int i = blockIdx.x * blockDim.x + threadIdx.x;
    if (i >= N_NODES * 16) return;
    int node = i >> 4;
    float s = inv[node];
    float4 v = reinterpret_cast<const float4*>(in)[i];
    v.x *= s; v.y *= s; v.z *= s; v.w *= s;
    reinterpret_cast<float4*>(g_xs)[i] = v;
    reinterpret_cast<float4*>(g_agg)[i] = make_float4(0.f, 0.f, 0.f, 0.f);
}

// ---------------- scatter-add (edge phase) -----------------------------------
// 16 threads per edge; each moves one float4 from xs[src] into agg[dst].
__global__ void k_scatter(const int* __restrict__ sArr, const int* __restrict__ dArr) {
    int gid = blockIdx.x * blockDim.x + threadIdx.x;
    int e = gid >> 4;
    if (e >= N_EDGES) return;
    int q = gid & 15;
    int s = sArr[e];
    int d = dArr[e];
    float4 v = reinterpret_cast<const float4*>(g_xs)[s * 16 + q];
    float* p = &g_agg[d * 64 + q * 4];
    unsigned long long gp = (unsigned long long)__cvta_generic_to_global(p);
    asm volatile("red.global.add.v4.f32 [%0], {%1,%2,%3,%4};"
                 :: "l"(gp), "f"(v.x), "f"(v.y), "f"(v.z), "f"(v.w)
                 : "memory");
}

// ---------------- fused concat-GEMM (+bias, optional relu) -------------------
// out[v,:] = act([xcur[v,:], g_agg[v,:]] @ W + b),  W is [128][64] row-major.
// 64 nodes per block, 256 threads (16x16), 4x4 register tile per thread.
// smem: W 32KB + A half-tile 16KB = 48KB static.
__global__ void k_gemm(const float* __restrict__ xcur,
                       const float* __restrict__ W,
                       const float* __restrict__ b,
                       float* __restrict__ out,
                       int doRelu) {
    __shared__ float Wsh[128][64];   // 32 KB
    __shared__ float Ash[64][64];    // 16 KB (one 64-wide half of the concat input)

    int tid = threadIdx.x;
    int row0 = blockIdx.x * 64;
    int ty = tid >> 4;       // 0..15
    int tx = tid & 15;       // 0..15

    // load W (8192 floats = 2048 float4)
    {
        const float4* W4 = reinterpret_cast<const float4*>(W);
        float4* Wsh4 = reinterpret_cast<float4*>(&Wsh[0][0]);
        #pragma unroll
        for (int i = 0; i < 8; ++i) Wsh4[tid + i * 256] = W4[tid + i * 256];
    }

    float acc[4][4];
    #pragma unroll
    for (int i = 0; i < 4; ++i)
        #pragma unroll
        for (int j = 0; j < 4; ++j) acc[i][j] = 0.f;

    #pragma unroll
    for (int p = 0; p < 2; ++p) {
        // stage the p-th half of the concat input: xcur (p=0) or g_agg (p=1)
        const float4* src4 = reinterpret_cast<const float4*>(p == 0 ? xcur : (const float*)g_agg);
        {
            float4* Ash4 = reinterpret_cast<float4*>(&Ash[0][0]);
            #pragma unroll
            for (int ii = 0; ii < 4; ++ii) {
                int i = tid + ii * 256;          // 0..1023
                int node = i >> 4;
                int gnode = row0 + node;
                float4 v = make_float4(0.f, 0.f, 0.f, 0.f);
                if (gnode < N_NODES) v = src4[gnode * 16 + (i & 15)];
                Ash4[i] = v;
            }
        }
        __syncthreads();

        #pragma unroll 16
        for (int k = 0; k < 64; ++k) {
            float4 w = *reinterpret_cast<const float4*>(&Wsh[p * 64 + k][tx * 4]);
            float a0 = Ash[ty * 4 + 0][k];
            float a1 = Ash[ty * 4 + 1][k];
            float a2 = Ash[ty * 4 + 2][k];
            float a3 = Ash[ty * 4 + 3][k];
            acc[0][0] += a0 * w.x; acc[0][1] += a0 * w.y; acc[0][2] += a0 * w.z; acc[0][3] += a0 * w.w;
            acc[1][0] += a1 * w.x; acc[1][1] += a1 * w.y; acc[1][2] += a1 * w.z; acc[1][3] += a1 * w.w;
            acc[2][0] += a2 * w.x; acc[2][1] += a2 * w.y; acc[2][2] += a2 * w.z; acc[2][3] += a2 * w.w;
            acc[3][0] += a3 * w.x; acc[3][1] += a3 * w.y; acc[3][2] += a3 * w.z; acc[3][3] += a3 * w.w;
        }
        __syncthreads();
    }

    float4 bb = *reinterpret_cast<const float4*>(&b[tx * 4]);
    #pragma unroll
    for (int i = 0; i < 4; ++i) {
        int row = row0 + ty * 4 + i;
        if (row < N_NODES) {
            float4 o;
            o.x = acc[i][0] + bb.x;
            o.y = acc[i][1] + bb.y;
            o.z = acc[i][2] + bb.z;
            o.w = acc[i][3] + bb.w;
            if (doRelu) {
                o.x = fmaxf(o.x, 0.f); o.y = fmaxf(o.y, 0.f);
                o.z = fmaxf(o.z, 0.f); o.w = fmaxf(o.w, 0.f);
            }
            reinterpret_cast<float4*>(out)[row * 16 + tx] = o;
        }
    }
}

// ---------------- launch ------------------------------------------------------
extern "C" void kernel_launch(void* const* d_in, const int* in_sizes, int n_in,
                              void* d_out, int out_size) {
    const float* x   = (const float*)d_in[0];
    const int*   src = (const int*)  d_in[1];
    const int*   dst = (const int*)  d_in[2];
    const float* W1  = (const float*)d_in[3];
    const float* b1  = (const float*)d_in[4];
    const float* W2  = (const float*)d_in[5];
    const float* b2  = (const float*)d_in[6];
    const float* W3  = (const float*)d_in[7];
    const float* b3  = (const float*)d_in[8];
    float* out = (float*)d_out;

    const int TB = 256;
    const int gN      = (N_NODES + TB - 1) / TB;            // 391
    const int gE      = (N_EDGES + TB - 1) / TB;            // 3907
    const int gScale  = (N_NODES * 16 + TB - 1) / TB;       // 6250
    const int gScat   = (N_EDGES * 16) / TB;                // 62500
    const int gGemm   = (N_NODES + 63) / 64;                // 1563

    // get scratch symbol addresses (device-side kernels reference symbols directly)
    float* h1p; cudaGetSymbolAddress((void**)&h1p, g_h1);
    float* h2p; cudaGetSymbolAddress((void**)&h2p, g_h2);

    // degrees (recomputed every call — deterministic work)
    k_zero_deg<<<gN, TB>>>();
    k_degree <<<gE, TB>>>(src, dst);
    k_inv    <<<gN, TB>>>();

    float* invo; cudaGetSymbolAddress((void**)&invo, g_invo);
    float* invi; cudaGetSymbolAddress((void**)&invi, g_invi);
    float* invu; cudaGetSymbolAddress((void**)&invu, g_invu);

    // Layer 1: 'O'  (src -> dst, norm by out-degree)
    k_scale_zero<<<gScale, TB>>>(x, invo);
    k_scatter   <<<gScat, TB>>>(src, dst);
    k_gemm      <<<gGemm, TB>>>(x, W1, b1, h1p, 1);

    // Layer 2: 'I'  (dst -> src, norm by in-degree)
    k_scale_zero<<<gScale, TB>>>(h1p, invi);
    k_scatter   <<<gScat, TB>>>(dst, src);
    k_gemm      <<<gGemm, TB>>>(h1p, W2, b2, h2p, 1);

    // Layer 3: 'U'  (both directions, norm by total degree), no relu
    k_scale_zero<<<gScale, TB>>>(h2p, invu);
    k_scatter   <<<gScat, TB>>>(src, dst);
    k_scatter   <<<gScat, TB>>>(dst, src);
    k_gemm      <<<gGemm, TB>>>(h2p, W3, b3, out, 0);
}

// round 2
// speedup vs baseline: 1.3278x; 1.3278x over previous
#include <cuda_runtime.h>
#include <cstdint>

#define N_NODES 100000
#define N_EDGES 1000000
#define F 64
#define SCAN_B 1024
#define SCAN_NBLK 98   // ceil(100000/1024)

// ---------------- scratch (static device globals; no allocation) -------------
__device__ float g_agg[N_NODES * F];   // aggregation output (gather writes fully)
__device__ float g_h1 [N_NODES * F];
__device__ float g_h2 [N_NODES * F];

__device__ int   g_cnt_in [N_NODES];
__device__ int   g_cnt_out[N_NODES];
__device__ int   g_off_in [N_NODES + 1];
__device__ int   g_off_out[N_NODES + 1];
__device__ int   g_cur_in [N_NODES];
__device__ int   g_cur_out[N_NODES];
__device__ int   g_csr_in [N_EDGES];   // for each dst row: list of src
__device__ int   g_csr_out[N_EDGES];   // for each src row: list of dst
__device__ int   g_bsum[2 * SCAN_NBLK];

__device__ float g_invo[N_NODES];
__device__ float g_invi[N_NODES];
__device__ float g_invu[N_NODES];

// ---------------- CSR build ---------------------------------------------------
__global__ void k_zero_cnt() {
    int i = blockIdx.x * blockDim.x + threadIdx.x;
    if (i < N_NODES) { g_cnt_in[i] = 0; g_cnt_out[i] = 0; }
}

__global__ void k_count(const int* __restrict__ src, const int* __restrict__ dst) {
    int e = blockIdx.x * blockDim.x + threadIdx.x;
    if (e < N_EDGES) {
        atomicAdd(&g_cnt_out[src[e]], 1);
        atomicAdd(&g_cnt_in [dst[e]], 1);
    }
}

__global__ void k_inv() {
    int i = blockIdx.x * blockDim.x + threadIdx.x;
    if (i < N_NODES) {
        float o = (float)g_cnt_out[i], d = (float)g_cnt_in[i];
        g_invo[i] = 1.f / fmaxf(o, 1.f);
        g_invi[i] = 1.f / fmaxf(d, 1.f);
        g_invu[i] = 1.f / fmaxf(o + d, 1.f);
    }
}

// block-level exclusive scan of counts; 196 blocks: [0,98)=in, [98,196)=out
__global__ void k_scan1() {
    __shared__ int sh[SCAN_B];
    int arr = blockIdx.x / SCAN_NBLK;         // 0=in 1=out
    int blk = blockIdx.x % SCAN_NBLK;
    int tid = threadIdx.x;
    int idx = blk * SCAN_B + tid;
    const int* cnt = arr ? g_cnt_out : g_cnt_in;
    int v = (idx < N_NODES) ? cnt[idx] : 0;
    sh[tid] = v;
    __syncthreads();
    #pragma unroll
    for (int o = 1; o < SCAN_B; o <<= 1) {
        int t = (tid >= o) ? sh[tid - o] : 0;
        __syncthreads();
        sh[tid] += t;
        __syncthreads();
    }
    int incl = sh[tid];
    int* off = arr ? g_off_out : g_off_in;
    if (idx < N_NODES) off[idx] = incl - v;   // exclusive
    if (tid == SCAN_B - 1) g_bsum[blockIdx.x] = incl;
}

__global__ void k_scan2() {
    int tid = threadIdx.x;
    if (tid < 2) {
        int base = tid * SCAN_NBLK;
        int run = 0;
        for (int i = 0; i < SCAN_NBLK; ++i) {
            int t = g_bsum[base + i];
            g_bsum[base + i] = run;
            run += t;
        }
    }
}

__global__ void k_scan3() {
    int i = blockIdx.x * blockDim.x + threadIdx.x;
    if (i < N_NODES) {
        int blk = i / SCAN_B;
        int oi = g_off_in [i] + g_bsum[blk];
        int oo = g_off_out[i] + g_bsum[SCAN_NBLK + blk];
        g_off_in [i] = oi;  g_cur_in [i] = oi;
        g_off_out[i] = oo;  g_cur_out[i] = oo;
    }
    if (i == 0) { g_off_in[N_NODES] = N_EDGES; g_off_out[N_NODES] = N_EDGES; }
}

__global__ void k_fill(const int* __restrict__ src, const int* __restrict__ dst) {
    int e = blockIdx.x * blockDim.x + threadIdx.x;
    if (e < N_EDGES) {
        int s = src[e], d = dst[e];
        int p = atomicAdd(&g_cur_in [d], 1); g_csr_in [p] = s;
        int q = atomicAdd(&g_cur_out[s], 1); g_csr_out[q] = d;
    }
}

// ---------------- gather aggregation ------------------------------------------
// 16 threads per node, each owns a float4 feature quarter. Optionally two CSRs
// (for the undirected layer). Normalization applied at neighbor read.
__global__ void k_gather(const int* __restrict__ off1, const int* __restrict__ csr1,
                         const int* __restrict__ off2, const int* __restrict__ csr2,
                         const float* __restrict__ xin, const float* __restrict__ inv) {
    int tid = blockIdx.x * blockDim.x + threadIdx.x;
    int node = tid >> 4;
    if (node >= N_NODES) return;
    int q = tid & 15;
    const float4* x4 = reinterpret_cast<const float4*>(xin);

    float4 acc = make_float4(0.f, 0.f, 0.f, 0.f);

    int jb = off1[node], je = off1[node + 1];
    for (int j = jb; j < je; ++j) {
        int nb = csr1[j];
        float s = inv[nb];
        float4 v = x4[nb * 16 + q];
        acc.x += v.x * s; acc.y += v.y * s; acc.z += v.z * s; acc.w += v.w * s;
    }
    if (csr2) {
        jb = off2[node]; je = off2[node + 1];
        for (int j = jb; j < je; ++j) {
            int nb = csr2[j];
            float s = inv[nb];
            float4 v = x4[nb * 16 + q];
            acc.x += v.x * s; acc.y += v.y * s; acc.z += v.z * s; acc.w += v.w * s;
        }
    }
    reinterpret_cast<float4*>(g_agg)[node * 16 + q] = acc;
}

// ---------------- fused concat-GEMM (+bias, optional relu) -------------------
__global__ void k_gemm(const float* __restrict__ xcur,
                       const float* __restrict__ W,
                       const float* __restrict__ b,
                       float* __restrict__ out,
                       int doRelu) {
    __shared__ float Wsh[128][64];   // 32 KB
    __shared__ float Ash[64][64];    // 16 KB

    int tid = threadIdx.x;
    int row0 = blockIdx.x * 64;
    int ty = tid >> 4;
    int tx = tid & 15;

    {
        const float4* W4 = reinterpret_cast<const float4*>(W);
        float4* Wsh4 = reinterpret_cast<float4*>(&Wsh[0][0]);
        #pragma unroll
        for (int i = 0; i < 8; ++i) Wsh4[tid + i * 256] = W4[tid + i * 256];
    }

    float acc[4][4];
    #pragma unroll
    for (int i = 0; i < 4; ++i)
        #pragma unroll
        for (int j = 0; j < 4; ++j) acc[i][j] = 0.f;

    #pragma unroll
    for (int p = 0; p < 2; ++p) {
        const float4* src4 = reinterpret_cast<const float4*>(p == 0 ? xcur : (const float*)g_agg);
        {
            float4* Ash4 = reinterpret_cast<float4*>(&Ash[0][0]);
            #pragma unroll
            for (int ii = 0; ii < 4; ++ii) {
                int i = tid + ii * 256;
                int gnode = row0 + (i >> 4);
                float4 v = make_float4(0.f, 0.f, 0.f, 0.f);
                if (gnode < N_NODES) v = src4[gnode * 16 + (i & 15)];
                Ash4[i] = v;
            }
        }
        __syncthreads();

        #pragma unroll 16
        for (int k = 0; k < 64; ++k) {
            float4 w = *reinterpret_cast<const float4*>(&Wsh[p * 64 + k][tx * 4]);
            float a0 = Ash[ty * 4 + 0][k];
            float a1 = Ash[ty * 4 + 1][k];
            float a2 = Ash[ty * 4 + 2][k];
            float a3 = Ash[ty * 4 + 3][k];
            acc[0][0] += a0 * w.x; acc[0][1] += a0 * w.y; acc[0][2] += a0 * w.z; acc[0][3] += a0 * w.w;
            acc[1][0] += a1 * w.x; acc[1][1] += a1 * w.y; acc[1][2] += a1 * w.z; acc[1][3] += a1 * w.w;
            acc[2][0] += a2 * w.x; acc[2][1] += a2 * w.y; acc[2][2] += a2 * w.z; acc[2][3] += a2 * w.w;
            acc[3][0] += a3 * w.x; acc[3][1] += a3 * w.y; acc[3][2] += a3 * w.z; acc[3][3] += a3 * w.w;
        }
        __syncthreads();
    }

    float4 bb = *reinterpret_cast<const float4*>(&b[tx * 4]);
    #pragma unroll
    for (int i = 0; i < 4; ++i) {
        int row = row0 + ty * 4 + i;
        if (row < N_NODES) {
            float4 o;
            o.x = acc[i][0] + bb.x;
            o.y = acc[i][1] + bb.y;
            o.z = acc[i][2] + bb.z;
            o.w = acc[i][3] + bb.w;
            if (doRelu) {
                o.x = fmaxf(o.x, 0.f); o.y = fmaxf(o.y, 0.f);
                o.z = fmaxf(o.z, 0.f); o.w = fmaxf(o.w, 0.f);
            }
            reinterpret_cast<float4*>(out)[row * 16 + tx] = o;
        }
    }
}

// ---------------- launch ------------------------------------------------------
extern "C" void kernel_launch(void* const* d_in, const int* in_sizes, int n_in,
                              void* d_out, int out_size) {
    const float* x   = (const float*)d_in[0];
    const int*   src = (const int*)  d_in[1];
    const int*   dst = (const int*)  d_in[2];
    const float* W1  = (const float*)d_in[3];
    const float* b1  = (const float*)d_in[4];
    const float* W2  = (const float*)d_in[5];
    const float* b2  = (const float*)d_in[6];
    const float* W3  = (const float*)d_in[7];
    const float* b3  = (const float*)d_in[8];
    float* out = (float*)d_out;

    const int TB = 256;
    const int gN    = (N_NODES + TB - 1) / TB;
    const int gE    = (N_EDGES + TB - 1) / TB;
    const int gGath = (N_NODES * 16 + TB - 1) / TB;
    const int gGemm = (N_NODES + 63) / 64;

    float* h1p;  cudaGetSymbolAddress((void**)&h1p,  g_h1);
    float* h2p;  cudaGetSymbolAddress((void**)&h2p,  g_h2);
    float* invo; cudaGetSymbolAddress((void**)&invo, g_invo);
    float* invi; cudaGetSymbolAddress((void**)&invi, g_invi);
    float* invu; cudaGetSymbolAddress((void**)&invu, g_invu);
    int* off_in;  cudaGetSymbolAddress((void**)&off_in,  g_off_in);
    int* off_out; cudaGetSymbolAddress((void**)&off_out, g_off_out);
    int* csr_in;  cudaGetSymbolAddress((void**)&csr_in,  g_csr_in);
    int* csr_out; cudaGetSymbolAddress((void**)&csr_out, g_csr_out);

    // ---- CSR build (per call; deterministic workload) ----
    k_zero_cnt<<<gN, TB>>>();
    k_count   <<<gE, TB>>>(src, dst);
    k_inv     <<<gN, TB>>>();
    k_scan1   <<<2 * SCAN_NBLK, SCAN_B>>>();
    k_scan2   <<<1, 32>>>();
    k_scan3   <<<gN, TB>>>();
    k_fill    <<<gE, TB>>>(src, dst);

    // Layer 1: 'O' — aggregate over in-edges at dst; neighbors are src, norm invo
    k_gather<<<gGath, TB>>>(off_in, csr_in, nullptr, nullptr, x, invo);
    k_gemm  <<<gGemm, TB>>>(x, W1, b1, h1p, 1);

    // Layer 2: 'I' — aggregate over out-edges at src; neighbors are dst, norm invi
    k_gather<<<gGath, TB>>>(off_out, csr_out, nullptr, nullptr, h1p, invi);
    k_gemm  <<<gGemm, TB>>>(h1p, W2, b2, h2p, 1);

    // Layer 3: 'U' — both directions, norm invu, no relu
    k_gather<<<gGath, TB>>>(off_in, csr_in, off_out, csr_out, h2p, invu);
    k_gemm  <<<gGemm, TB>>>(h2p, W3, b3, out, 0);
}

// round 4
// speedup vs baseline: 1.3848x; 1.0429x over previous
#include <cuda_runtime.h>
#include <cuda_bf16.h>
#include <cstdint>

#define N_NODES 100000
#define N_EDGES 1000000
#define F 64
#define SCAN_B 1024
#define SCAN_NBLK 98   // ceil(100000/1024)

// ---------------- scratch (static device globals; no allocation) -------------
__device__ __align__(256) float g_agg[N_NODES * F];
__device__ __align__(256) float g_h1 [N_NODES * F];
__device__ __align__(256) float g_h2 [N_NODES * F];
// pre-split weights: [layer][s(hi/lo)][n=64][k=128] bf16
__device__ __align__(256) __nv_bfloat16 g_Wt[3 * 2 * 64 * 128];

__device__ int   g_cnt_in [N_NODES];
__device__ int   g_cnt_out[N_NODES];
__device__ int   g_off_in [N_NODES + 1];
__device__ int   g_off_out[N_NODES + 1];
__device__ int   g_cur_in [N_NODES];
__device__ int   g_cur_out[N_NODES];
__device__ int   g_csr_in [N_EDGES];
__device__ int   g_csr_out[N_EDGES];
__device__ int   g_bsum[2 * SCAN_NBLK];

__device__ float g_invo[N_NODES];
__device__ float g_invi[N_NODES];
__device__ float g_invu[N_NODES];

// ---------------- CSR build ---------------------------------------------------
__global__ void k_zero_cnt() {
    int i = blockIdx.x * blockDim.x + threadIdx.x;
    if (i < N_NODES) { g_cnt_in[i] = 0; g_cnt_out[i] = 0; }
}
__global__ void k_count(const int* __restrict__ src, const int* __restrict__ dst) {
    int e = blockIdx.x * blockDim.x + threadIdx.x;
    if (e < N_EDGES) {
        atomicAdd(&g_cnt_out[src[e]], 1);
        atomicAdd(&g_cnt_in [dst[e]], 1);
    }
}
__global__ void k_scan1() {
    __shared__ int sh[SCAN_B];
    int arr = blockIdx.x / SCAN_NBLK;
    int blk = blockIdx.x % SCAN_NBLK;
    int tid = threadIdx.x;
    int idx = blk * SCAN_B + tid;
    const int* cnt = arr ? g_cnt_out : g_cnt_in;
    int v = (idx < N_NODES) ? cnt[idx] : 0;
    sh[tid] = v;
    __syncthreads();
    #pragma unroll
    for (int o = 1; o < SCAN_B; o <<= 1) {
        int t = (tid >= o) ? sh[tid - o] : 0;
        __syncthreads();
        sh[tid] += t;
        __syncthreads();
    }
    int incl = sh[tid];
    int* off = arr ? g_off_out : g_off_in;
    if (idx < N_NODES) off[idx] = incl - v;
    if (tid == SCAN_B - 1) g_bsum[blockIdx.x] = incl;
}
__global__ void k_scan2() {   // 1 block, 256 threads; two independent 98-scans
    __shared__ int sh[256];
    int t = threadIdx.x;
    int arr = t >> 7, i = t & 127;
    int v = (i < SCAN_NBLK) ? g_bsum[arr * SCAN_NBLK + i] : 0;
    sh[t] = v;
    __syncthreads();
    #pragma unroll
    for (int o = 1; o < 128; o <<= 1) {
        int u = (i >= o) ? sh[arr * 128 + i - o] : 0;
        __syncthreads();
        sh[t] += u;
        __syncthreads();
    }
    if (i < SCAN_NBLK) g_bsum[arr * SCAN_NBLK + i] = sh[t] - v;  // exclusive
}
__global__ void k_scan3() {
    int i = blockIdx.x * blockDim.x + threadIdx.x;
    if (i < N_NODES) {
        int blk = i / SCAN_B;
        int oi = g_off_in [i] + g_bsum[blk];
        int oo = g_off_out[i] + g_bsum[SCAN_NBLK + blk];
        g_off_in [i] = oi;  g_cur_in [i] = oi;
        g_off_out[i] = oo;  g_cur_out[i] = oo;
        float o = (float)g_cnt_out[i], d = (float)g_cnt_in[i];
        g_invo[i] = 1.f / fmaxf(o, 1.f);
        g_invi[i] = 1.f / fmaxf(d, 1.f);
        g_invu[i] = 1.f / fmaxf(o + d, 1.f);
    }
    if (i == 0) { g_off_in[N_NODES] = N_EDGES; g_off_out[N_NODES] = N_EDGES; }
}
__global__ void k_fill(const int* __restrict__ src, const int* __restrict__ dst) {
    int e = blockIdx.x * blockDim.x + threadIdx.x;
    if (e < N_EDGES) {
        int s = src[e], d = dst[e];
        int p = atomicAdd(&g_cur_in [d], 1); g_csr_in [p] = s;
        int q = atomicAdd(&g_cur_out[s], 1); g_csr_out[q] = d;
    }
}

// ---------------- weight prep: split fp32 -> bf16 hi/lo, transpose -----------
// g_Wt[l][s][n][k] = split_s(W_l[k][n])
__global__ void k_prepW(const float* __restrict__ W1, const float* __restrict__ W2,
                        const float* __restrict__ W3) {
    int idx = blockIdx.x * blockDim.x + threadIdx.x;
    if (idx >= 3 * 8192) return;
    int l = idx / 8192, r = idx % 8192;
    int k = r >> 6, n = r & 63;
    const float* W = (l == 0) ? W1 : (l == 1) ? W2 : W3;
    float v = W[k * 64 + n];
    __nv_bfloat16 hi = __float2bfloat16(v);
    __nv_bfloat16 lo = __float2bfloat16(v - __bfloat162float(hi));
    g_Wt[((l * 2 + 0) * 64 + n) * 128 + k] = hi;
    g_Wt[((l * 2 + 1) * 64 + n) * 128 + k] = lo;
}

// ---------------- gather aggregation ------------------------------------------
__global__ void k_gather(const int* __restrict__ off1, const int* __restrict__ csr1,
                         const int* __restrict__ off2, const int* __restrict__ csr2,
                         const float* __restrict__ xin, const float* __restrict__ inv) {
    int tid = blockIdx.x * blockDim.x + threadIdx.x;
    int node = tid >> 4;
    if (node >= N_NODES) return;
    int q = tid & 15;
    const float4* x4 = reinterpret_cast<const float4*>(xin);
    float4 acc = make_float4(0.f, 0.f, 0.f, 0.f);
    int jb = off1[node], je = off1[node + 1];
    for (int j = jb; j < je; ++j) {
        int nb = csr1[j];
        float s = inv[nb];
        float4 v = x4[nb * 16 + q];
        acc.x += v.x * s; acc.y += v.y * s; acc.z += v.z * s; acc.w += v.w * s;
    }
    if (csr2) {
        jb = off2[node]; je = off2[node + 1];
        for (int j = jb; j < je; ++j) {
            int nb = csr2[j];
            float s = inv[nb];
            float4 v = x4[nb * 16 + q];
            acc.x += v.x * s; acc.y += v.y * s; acc.z += v.z * s; acc.w += v.w * s;
        }
    }
    reinterpret_cast<float4*>(g_agg)[node * 16 + q] = acc;
}

// ---------------- tensor-core concat-GEMM via mma.sync (bf16 split) ----------
// D[128 x 64] = [xcur | g_agg](128 x 128) @ W(128 x 64) + b, fp32 accum.
// smem (bf16, padded k-stride 136):
//   Ahi[128][136]  @ 0        (34816 B)
//   Alo[128][136]  @ 34816
//   Bhi[ 64][136]  @ 69632    (17408 B)
//   Blo[ 64][136]  @ 87040
#define AST 136
#define SM_AHI 0
#define SM_ALO 34816
#define SM_BHI 69632
#define SM_BLO 87040
#define SM_TOT 104448

__device__ __forceinline__ uint32_t smem_u32(const void* p) {
    uint32_t a;
    asm("{ .reg .u64 t; cvta.to.shared.u64 t, %1; cvt.u32.u64 %0, t; }" : "=r"(a) : "l"(p));
    return a;
}
__device__ __forceinline__ void ldsm_x4(uint32_t& r0, uint32_t& r1, uint32_t& r2, uint32_t& r3,
                                        uint32_t addr) {
    asm volatile("ldmatrix.sync.aligned.m8n8.x4.shared.b16 {%0,%1,%2,%3}, [%4];"
                 : "=r"(r0), "=r"(r1), "=r"(r2), "=r"(r3) : "r"(addr));
}
__device__ __forceinline__ void ldsm_x2(uint32_t& r0, uint32_t& r1, uint32_t addr) {
    asm volatile("ldmatrix.sync.aligned.m8n8.x2.shared.b16 {%0,%1}, [%2];"
                 : "=r"(r0), "=r"(r1) : "r"(addr));
}
__device__ __forceinline__ void mma_bf16(float* c, const uint32_t* a, uint32_t b0, uint32_t b1) {
    asm volatile(
        "mma.sync.aligned.m16n8k16.row.col.f32.bf16.bf16.f32 "
        "{%0,%1,%2,%3}, {%4,%5,%6,%7}, {%8,%9}, {%0,%1,%2,%3};"
        : "+f"(c[0]), "+f"(c[1]), "+f"(c[2]), "+f"(c[3])
        : "r"(a[0]), "r"(a[1]), "r"(a[2]), "r"(a[3]), "r"(b0), "r"(b1));
}

__global__ void __launch_bounds__(256, 1) k_gemm_mma(
        const float* __restrict__ xcur, const __nv_bfloat16* __restrict__ Wt,
        const float* __restrict__ bias, float* __restrict__ out, int doRelu) {
    extern __shared__ char smem[];
    uint32_t sb = smem_u32(smem);
    int tid = threadIdx.x;
    int w = tid >> 5, l = tid & 31;
    int row0 = blockIdx.x * 128;

    // ---- stage W hi/lo into smem (each [64][128] bf16 -> padded [64][136]) ----
    {
        const uint4* whi = reinterpret_cast<const uint4*>(Wt);            // hi: 1024 uint4
        const uint4* wlo = reinterpret_cast<const uint4*>(Wt + 64 * 128); // lo
        #pragma unroll
        for (int i = 0; i < 4; ++i) {
            int c = tid + i * 256;          // 0..1023 ; n = c/16, chunk = c%16 (8 bf16 each)
            int n = c >> 4, ch = c & 15;
            *reinterpret_cast<uint4*>(smem + SM_BHI + (n * AST + ch * 8) * 2) = whi[c];
            *reinterpret_cast<uint4*>(smem + SM_BLO + (n * AST + ch * 8) * 2) = wlo[c];
        }
    }

    // ---- convert A (concat of xcur | g_agg) to bf16 hi/lo smem ----
    {
        int r = tid >> 1;                  // 0..127
        int half = tid & 1;                // 0: xcur cols 0-63, 1: agg cols 64-127
        int gnode = row0 + r;
        bool ok = gnode < N_NODES;
        const float4* s4 = reinterpret_cast<const float4*>(half ? (const float*)g_agg : xcur);
        #pragma unroll
        for (int j = 0; j < 16; ++j) {
            float4 v = ok ? s4[gnode * 16 + j] : make_float4(0.f, 0.f, 0.f, 0.f);
            __nv_bfloat16 hx = __float2bfloat16(v.x), hy = __float2bfloat16(v.y);
            __nv_bfloat16 hz = __float2bfloat16(v.z), hw = __float2bfloat16(v.w);
            __nv_bfloat16 lx = __float2bfloat16(v.x - __bfloat162float(hx));
            __nv_bfloat16 ly = __float2bfloat16(v.y - __bfloat162float(hy));
            __nv_bfloat16 lz = __float2bfloat16(v.z - __bfloat162float(hz));
            __nv_bfloat16 lw = __float2bfloat16(v.w - __bfloat162float(hw));
            uint32_t h01 = (uint32_t)__bfloat16_as_ushort(hx) | ((uint32_t)__bfloat16_as_ushort(hy) << 16);
            uint32_t h23 = (uint32_t)__bfloat16_as_ushort(hz) | ((uint32_t)__bfloat16_as_ushort(hw) << 16);
            uint32_t l01 = (uint32_t)__bfloat16_as_ushort(lx) | ((uint32_t)__bfloat16_as_ushort(ly) << 16);
            uint32_t l23 = (uint32_t)__bfloat16_as_ushort(lz) | ((uint32_t)__bfloat16_as_ushort(lw) << 16);
            int col = half * 64 + j * 4;
            *reinterpret_cast<uint2*>(smem + SM_AHI + (r * AST + col) * 2) = make_uint2(h01, h23);
            *reinterpret_cast<uint2*>(smem + SM_ALO + (r * AST + col) * 2) = make_uint2(l01, l23);
        }
    }
    __syncthreads();

    // ---- MMA mainloop: warp w -> rows [w*16, w*16+16), all 64 cols ----
    float acc[8][4];
    #pragma unroll
    for (int nt = 0; nt < 8; ++nt)
        #pragma unroll
        for (int i = 0; i < 4; ++i) acc[nt][i] = 0.f;

    // ldmatrix lane addressing
    int a_row = w * 16 + (l & 7) + ((l >> 3) & 1) * 8;
    int a_colq = (l >> 4) * 8;                 // 0 or 8
    int b_nrow = (l & 7);
    int b_kq = ((l >> 3) & 1) * 8;

    #pragma unroll
    for (int kt = 0; kt < 8; ++kt) {
        uint32_t ahi[4], alo[4];
        uint32_t aaddr = sb + SM_AHI + (a_row * AST + kt * 16 + a_colq) * 2;
        ldsm_x4(ahi[0], ahi[1], ahi[2], ahi[3], aaddr);
        uint32_t aaddr2 = sb + SM_ALO + (a_row * AST + kt * 16 + a_colq) * 2;
        ldsm_x4(alo[0], alo[1], alo[2], alo[3], aaddr2);

        #pragma unroll
        for (int nt = 0; nt < 8; ++nt) {
            uint32_t bhi0, bhi1, blo0, blo1;
            uint32_t baddr = sb + SM_BHI + ((nt * 8 + b_nrow) * AST + kt * 16 + b_kq) * 2;
            ldsm_x2(bhi0, bhi1, baddr);
            uint32_t baddr2 = sb + SM_BLO + ((nt * 8 + b_nrow) * AST + kt * 16 + b_kq) * 2;
            ldsm_x2(blo0, blo1, baddr2);
            mma_bf16(acc[nt], ahi, bhi0, bhi1);
            mma_bf16(acc[nt], ahi, blo0, blo1);
            mma_bf16(acc[nt], alo, bhi0, bhi1);
        }
    }

    // ---- epilogue: bias + relu, direct global float2 stores ----
    int r1 = row0 + w * 16 + (l >> 2);
    int r2 = r1 + 8;
    int cb = (l & 3) * 2;
    #pragma unroll
    for (int nt = 0; nt < 8; ++nt) {
        int col = nt * 8 + cb;
        float bx = bias[col], by = bias[col + 1];
        float2 o1 = make_float2(acc[nt][0] + bx, acc[nt][1] + by);
        float2 o2 = make_float2(acc[nt][2] + bx, acc[nt][3] + by);
        if (doRelu) {
            o1.x = fmaxf(o1.x, 0.f); o1.y = fmaxf(o1.y, 0.f);
            o2.x = fmaxf(o2.x, 0.f); o2.y = fmaxf(o2.y, 0.f);
        }
        if (r1 < N_NODES) *reinterpret_cast<float2*>(&out[r1 * 64 + col]) = o1;
        if (r2 < N_NODES) *reinterpret_cast<float2*>(&out[r2 * 64 + col]) = o2;
    }
}

// ---------------- launch ------------------------------------------------------
extern "C" void kernel_launch(void* const* d_in, const int* in_sizes, int n_in,
                              void* d_out, int out_size) {
    const float* x   = (const float*)d_in[0];
    const int*   src = (const int*)  d_in[1];
    const int*   dst = (const int*)  d_in[2];
    const float* W1  = (const float*)d_in[3];
    const float* b1  = (const float*)d_in[4];
    const float* W2  = (const float*)d_in[5];
    const float* b2  = (const float*)d_in[6];
    const float* W3  = (const float*)d_in[7];
    const float* b3  = (const float*)d_in[8];
    float* out = (float*)d_out;

    const int TB = 256;
    const int gN    = (N_NODES + TB - 1) / TB;
    const int gE    = (N_EDGES + TB - 1) / TB;
    const int gGath = (N_NODES * 16 + TB - 1) / TB;
    const int gGemm = (N_NODES + 127) / 128;   // 782

    cudaFuncSetAttribute(k_gemm_mma, cudaFuncAttributeMaxDynamicSharedMemorySize, SM_TOT);

    float* h1p;  cudaGetSymbolAddress((void**)&h1p,  g_h1);
    float* h2p;  cudaGetSymbolAddress((void**)&h2p,  g_h2);
    float* invo; cudaGetSymbolAddress((void**)&invo, g_invo);
    float* invi; cudaGetSymbolAddress((void**)&invi, g_invi);
    float* invu; cudaGetSymbolAddress((void**)&invu, g_invu);
    int* off_in;  cudaGetSymbolAddress((void**)&off_in,  g_off_in);
    int* off_out; cudaGetSymbolAddress((void**)&off_out, g_off_out);
    int* csr_in;  cudaGetSymbolAddress((void**)&csr_in,  g_csr_in);
    int* csr_out; cudaGetSymbolAddress((void**)&csr_out, g_csr_out);
    __nv_bfloat16* wt; cudaGetSymbolAddress((void**)&wt, g_Wt);

    // ---- CSR build ----
    k_zero_cnt<<<gN, TB>>>();
    k_count   <<<gE, TB>>>(src, dst);
    k_scan1   <<<2 * SCAN_NBLK, SCAN_B>>>();
    k_scan2   <<<1, 256>>>();
    k_scan3   <<<gN, TB>>>();
    k_fill    <<<gE, TB>>>(src, dst);
    k_prepW   <<<(3 * 8192 + TB - 1) / TB, TB>>>(W1, W2, W3);

    // Layer 1: 'O'
    k_gather  <<<gGath, TB>>>(off_in, csr_in, nullptr, nullptr, x, invo);
    k_gemm_mma<<<gGemm, 256, SM_TOT>>>(x, wt, b1, h1p, 1);

    // Layer 2: 'I'
    k_gather  <<<gGath, TB>>>(off_out, csr_out, nullptr, nullptr, h1p, invi);
    k_gemm_mma<<<gGemm, 256, SM_TOT>>>(h1p, wt + 2 * 8192, b2, h2p, 1);

    // Layer 3: 'U'
    k_gather  <<<gGath, TB>>>(off_in, csr_in, off_out, csr_out, h2p, invu);
    k_gemm_mma<<<gGemm, 256, SM_TOT>>>(h2p, wt + 4 * 8192, b3, out, 0);
}

// round 5
// speedup vs baseline: 1.7054x; 1.2315x over previous
#include <cuda_runtime.h>
#include <cuda_bf16.h>
#include <cstdint>

#define N_NODES 100000
#define N_EDGES 1000000
#define F 64
#define SCAN_B 1024
#define SCAN_NBLK 98   // ceil(100000/1024)

// ---------------- scratch (static device globals; no allocation) -------------
__device__ __align__(256) float g_h1 [N_NODES * F];
__device__ __align__(256) float g_h2 [N_NODES * F];
// pre-split weights: [layer][s(hi/lo)][n=64][k=128] bf16
__device__ __align__(256) __nv_bfloat16 g_Wt[3 * 2 * 64 * 128];

__device__ int   g_cnt_in [N_NODES];
__device__ int   g_cnt_out[N_NODES];
__device__ int   g_off_in [N_NODES + 1];
__device__ int   g_off_out[N_NODES + 1];
__device__ int   g_cur_in [N_NODES];
__device__ int   g_cur_out[N_NODES];
__device__ int   g_csr_in [N_EDGES];
__device__ int   g_csr_out[N_EDGES];
__device__ int   g_bsum[2 * SCAN_NBLK];

__device__ float g_invo[N_NODES];
__device__ float g_invi[N_NODES];
__device__ float g_invu[N_NODES];

// ---------------- CSR build ---------------------------------------------------
__global__ void k_zero_cnt() {
    int i = blockIdx.x * blockDim.x + threadIdx.x;
    if (i < N_NODES) { g_cnt_in[i] = 0; g_cnt_out[i] = 0; }
}
__global__ void k_count(const int* __restrict__ src, const int* __restrict__ dst) {
    int e = blockIdx.x * blockDim.x + threadIdx.x;
    if (e < N_EDGES) {
        atomicAdd(&g_cnt_out[src[e]], 1);
        atomicAdd(&g_cnt_in [dst[e]], 1);
    }
}
__global__ void k_scan1() {
    __shared__ int sh[SCAN_B];
    int arr = blockIdx.x / SCAN_NBLK;
    int blk = blockIdx.x % SCAN_NBLK;
    int tid = threadIdx.x;
    int idx = blk * SCAN_B + tid;
    const int* cnt = arr ? g_cnt_out : g_cnt_in;
    int v = (idx < N_NODES) ? cnt[idx] : 0;
    sh[tid] = v;
    __syncthreads();
    #pragma unroll
    for (int o = 1; o < SCAN_B; o <<= 1) {
        int t = (tid >= o) ? sh[tid - o] : 0;
        __syncthreads();
        sh[tid] += t;
        __syncthreads();
    }
    int incl = sh[tid];
    int* off = arr ? g_off_out : g_off_in;
    if (idx < N_NODES) off[idx] = incl - v;
    if (tid == SCAN_B - 1) g_bsum[blockIdx.x] = incl;
}
// scan3 with embedded block-sum scan (replaces old scan2+scan3)
__global__ void k_scan3() {
    __shared__ int sh[256];
    __shared__ int ex[256];
    int t = threadIdx.x;                       // 256 threads
    int arr = t >> 7, j = t & 127;
    int v = (j < SCAN_NBLK) ? g_bsum[arr * SCAN_NBLK + j] : 0;
    sh[t] = v;
    __syncthreads();
    #pragma unroll
    for (int o = 1; o < 128; o <<= 1) {
        int u = (j >= o) ? sh[arr * 128 + j - o] : 0;
        __syncthreads();
        sh[t] += u;
        __syncthreads();
    }
    ex[t] = sh[t] - v;                         // exclusive prefix of block sums
    __syncthreads();

    int i = blockIdx.x * blockDim.x + t;
    if (i < N_NODES) {
        int blk = i / SCAN_B;
        int oi = g_off_in [i] + ex[blk];
        int oo = g_off_out[i] + ex[128 + blk];
        g_off_in [i] = oi;  g_cur_in [i] = oi;
        g_off_out[i] = oo;  g_cur_out[i] = oo;
        float o = (float)g_cnt_out[i], d = (float)g_cnt_in[i];
        g_invo[i] = 1.f / fmaxf(o, 1.f);
        g_invi[i] = 1.f / fmaxf(d, 1.f);
        g_invu[i] = 1.f / fmaxf(o + d, 1.f);
    }
    if (i == 0) { g_off_in[N_NODES] = N_EDGES; g_off_out[N_NODES] = N_EDGES; }
}
__global__ void k_fill(const int* __restrict__ src, const int* __restrict__ dst) {
    int e = blockIdx.x * blockDim.x + threadIdx.x;
    if (e < N_EDGES) {
        int s = src[e], d = dst[e];
        int p = atomicAdd(&g_cur_in [d], 1); g_csr_in [p] = s;
        int q = atomicAdd(&g_cur_out[s], 1); g_csr_out[q] = d;
    }
}

// ---------------- weight prep: split fp32 -> bf16 hi/lo, transpose -----------
__global__ void k_prepW(const float* __restrict__ W1, const float* __restrict__ W2,
                        const float* __restrict__ W3) {
    int idx = blockIdx.x * blockDim.x + threadIdx.x;
    if (idx >= 3 * 8192) return;
    int l = idx / 8192, r = idx % 8192;
    int k = r >> 6, n = r & 63;
    const float* W = (l == 0) ? W1 : (l == 1) ? W2 : W3;
    float v = W[k * 64 + n];
    __nv_bfloat16 hi = __float2bfloat16(v);
    __nv_bfloat16 lo = __float2bfloat16(v - __bfloat162float(hi));
    g_Wt[((l * 2 + 0) * 64 + n) * 128 + k] = hi;
    g_Wt[((l * 2 + 1) * 64 + n) * 128 + k] = lo;
}

// ---------------- fused gather + concat-GEMM (bf16 split mma.sync) -----------
// Per block: 128 output rows. Gather agg rows (CSR, normalized) in registers,
// convert both halves of [xcur | agg] to bf16 hi/lo smem, then 16-warp MMA.
#define AST 136
#define SM_AHI 0
#define SM_ALO 34816
#define SM_BHI 69632
#define SM_BLO 87040
#define SM_TOT 104448

__device__ __forceinline__ uint32_t smem_u32(const void* p) {
    uint32_t a;
    asm("{ .reg .u64 t; cvta.to.shared.u64 t, %1; cvt.u32.u64 %0, t; }" : "=r"(a) : "l"(p));
    return a;
}
__device__ __forceinline__ void ldsm_x4(uint32_t& r0, uint32_t& r1, uint32_t& r2, uint32_t& r3,
                                        uint32_t addr) {
    asm volatile("ldmatrix.sync.aligned.m8n8.x4.shared.b16 {%0,%1,%2,%3}, [%4];"
                 : "=r"(r0), "=r"(r1), "=r"(r2), "=r"(r3) : "r"(addr));
}
__device__ __forceinline__ void ldsm_x2(uint32_t& r0, uint32_t& r1, uint32_t addr) {
    asm volatile("ldmatrix.sync.aligned.m8n8.x2.shared.b16 {%0,%1}, [%2];"
                 : "=r"(r0), "=r"(r1) : "r"(addr));
}
__device__ __forceinline__ void mma_bf16(float* c, const uint32_t* a, uint32_t b0, uint32_t b1) {
    asm volatile(
        "mma.sync.aligned.m16n8k16.row.col.f32.bf16.bf16.f32 "
        "{%0,%1,%2,%3}, {%4,%5,%6,%7}, {%8,%9}, {%0,%1,%2,%3};"
        : "+f"(c[0]), "+f"(c[1]), "+f"(c[2]), "+f"(c[3])
        : "r"(a[0]), "r"(a[1]), "r"(a[2]), "r"(a[3]), "r"(b0), "r"(b1));
}
__device__ __forceinline__ void cvt_store(char* smemBase, int r, int col, float4 v,
                                          char* smemBaseLo) {
    __nv_bfloat16 hx = __float2bfloat16(v.x), hy = __float2bfloat16(v.y);
    __nv_bfloat16 hz = __float2bfloat16(v.z), hw = __float2bfloat16(v.w);
    __nv_bfloat16 lx = __float2bfloat16(v.x - __bfloat162float(hx));
    __nv_bfloat16 ly = __float2bfloat16(v.y - __bfloat162float(hy));
    __nv_bfloat16 lz = __float2bfloat16(v.z - __bfloat162float(hz));
    __nv_bfloat16 lw = __float2bfloat16(v.w - __bfloat162float(hw));
    uint32_t h01 = (uint32_t)__bfloat16_as_ushort(hx) | ((uint32_t)__bfloat16_as_ushort(hy) << 16);
    uint32_t h23 = (uint32_t)__bfloat16_as_ushort(hz) | ((uint32_t)__bfloat16_as_ushort(hw) << 16);
    uint32_t l01 = (uint32_t)__bfloat16_as_ushort(lx) | ((uint32_t)__bfloat16_as_ushort(ly) << 16);
    uint32_t l23 = (uint32_t)__bfloat16_as_ushort(lz) | ((uint32_t)__bfloat16_as_ushort(lw) << 16);
    *reinterpret_cast<uint2*>(smemBase   + (r * AST + col) * 2) = make_uint2(h01, h23);
    *reinterpret_cast<uint2*>(smemBaseLo + (r * AST + col) * 2) = make_uint2(l01, l23);
}

__global__ void __launch_bounds__(512, 2) k_fused(
        const float* __restrict__ xcur,
        const int* __restrict__ off1, const int* __restrict__ csr1,
        const int* __restrict__ off2, const int* __restrict__ csr2,
        const float* __restrict__ inv,
        const __nv_bfloat16* __restrict__ Wt,
        const float* __restrict__ bias, float* __restrict__ out, int doRelu) {
    extern __shared__ char smem[];
    uint32_t sb = smem_u32(smem);
    int tid = threadIdx.x;
    int row0 = blockIdx.x * 128;
    const float4* x4 = reinterpret_cast<const float4*>(xcur);

    // ---- stage W hi/lo (64x128 bf16 each -> padded [64][136]) ----
    {
        const uint4* whi = reinterpret_cast<const uint4*>(Wt);
        const uint4* wlo = reinterpret_cast<const uint4*>(Wt + 64 * 128);
        #pragma unroll
        for (int i = 0; i < 2; ++i) {
            int c = tid + i * 512;          // 0..1023: n = c/16, ch = c%16
            int n = c >> 4, ch = c & 15;
            *reinterpret_cast<uint4*>(smem + SM_BHI + (n * AST + ch * 8) * 2) = whi[c];
            *reinterpret_cast<uint4*>(smem + SM_BLO + (n * AST + ch * 8) * 2) = wlo[c];
        }
    }

    // ---- x half: cols 0..63 (rows of this tile, coalesced) ----
    {
        #pragma unroll
        for (int i = 0; i < 4; ++i) {
            int idx = tid + i * 512;        // 0..2047
            int r = idx >> 4, j = idx & 15;
            int gnode = row0 + r;
            float4 v = (gnode < N_NODES) ? x4[gnode * 16 + j]
                                         : make_float4(0.f, 0.f, 0.f, 0.f);
            cvt_store(smem + SM_AHI, r, j * 4, v, smem + SM_ALO);
        }
    }

    // ---- gather half: cols 64..127 (16 threads per node) ----
    {
        int grp = tid >> 4;                 // 0..31
        int q = tid & 15;
        #pragma unroll
        for (int it = 0; it < 4; ++it) {
            int r = it * 32 + grp;          // 0..127
            int node = row0 + r;
            float4 acc = make_float4(0.f, 0.f, 0.f, 0.f);
            if (node < N_NODES) {
                int jb = off1[node], je = off1[node + 1];
                for (int j = jb; j < je; ++j) {
                    int nb = csr1[j];
                    float s = inv[nb];
                    float4 v = x4[nb * 16 + q];
                    acc.x += v.x * s; acc.y += v.y * s; acc.z += v.z * s; acc.w += v.w * s;
                }
                if (csr2) {
                    jb = off2[node]; je = off2[node + 1];
                    for (int j = jb; j < je; ++j) {
                        int nb = csr2[j];
                        float s = inv[nb];
                        float4 v = x4[nb * 16 + q];
                        acc.x += v.x * s; acc.y += v.y * s; acc.z += v.z * s; acc.w += v.w * s;
                    }
                }
            }
            cvt_store(smem + SM_AHI, r, 64 + q * 4, acc, smem + SM_ALO);
        }
    }
    __syncthreads();

    // ---- MMA mainloop: 16 warps. wm = rows [wm*16,+16), wn = cols [wn*32,+32) ----
    int w = tid >> 5, l = tid & 31;
    int wm = w & 7, wn = w >> 3;

    float acc[4][4];
    #pragma unroll
    for (int nt = 0; nt < 4; ++nt)
        #pragma unroll
        for (int i = 0; i < 4; ++i) acc[nt][i] = 0.f;

    int a_row = wm * 16 + (l & 7) + ((l >> 3) & 1) * 8;
    int a_colq = (l >> 4) * 8;
    int b_nrow = (l & 7);
    int b_kq = ((l >> 3) & 1) * 8;

    #pragma unroll
    for (int kt = 0; kt < 8; ++kt) {
        uint32_t ahi[4], alo[4];
        ldsm_x4(ahi[0], ahi[1], ahi[2], ahi[3],
                sb + SM_AHI + (a_row * AST + kt * 16 + a_colq) * 2);
        ldsm_x4(alo[0], alo[1], alo[2], alo[3],
                sb + SM_ALO + (a_row * AST + kt * 16 + a_colq) * 2);
        #pragma unroll
        for (int nt = 0; nt < 4; ++nt) {
            int brow = wn * 32 + nt * 8 + b_nrow;
            uint32_t bhi0, bhi1, blo0, blo1;
            ldsm_x2(bhi0, bhi1, sb + SM_BHI + (brow * AST + kt * 16 + b_kq) * 2);
            ldsm_x2(blo0, blo1, sb + SM_BLO + (brow * AST + kt * 16 + b_kq) * 2);
            mma_bf16(acc[nt], ahi, bhi0, bhi1);
            mma_bf16(acc[nt], ahi, blo0, blo1);
            mma_bf16(acc[nt], alo, bhi0, bhi1);
        }
    }

    // ---- epilogue: bias + relu, direct global float2 stores ----
    int r1 = row0 + wm * 16 + (l >> 2);
    int r2 = r1 + 8;
    int cb = (l & 3) * 2;
    #pragma unroll
    for (int nt = 0; nt < 4; ++nt) {
        int col = wn * 32 + nt * 8 + cb;
        float bx = bias[col], by = bias[col + 1];
        float2 o1 = make_float2(acc[nt][0] + bx, acc[nt][1] + by);
        float2 o2 = make_float2(acc[nt][2] + bx, acc[nt][3] + by);
        if (doRelu) {
            o1.x = fmaxf(o1.x, 0.f); o1.y = fmaxf(o1.y, 0.f);
            o2.x = fmaxf(o2.x, 0.f); o2.y = fmaxf(o2.y, 0.f);
        }
        if (r1 < N_NODES) *reinterpret_cast<float2*>(&out[r1 * 64 + col]) = o1;
        if (r2 < N_NODES) *reinterpret_cast<float2*>(&out[r2 * 64 + col]) = o2;
    }
}

// ---------------- launch ------------------------------------------------------
extern "C" void kernel_launch(void* const* d_in, const int* in_sizes, int n_in,
                              void* d_out, int out_size) {
    const float* x   = (const float*)d_in[0];
    const int*   src = (const int*)  d_in[1];
    const int*   dst = (const int*)  d_in[2];
    const float* W1  = (const float*)d_in[3];
    const float* b1  = (const float*)d_in[4];
    const float* W2  = (const float*)d_in[5];
    const float* b2  = (const float*)d_in[6];
    const float* W3  = (const float*)d_in[7];
    const float* b3  = (const float*)d_in[8];
    float* out = (float*)d_out;

    const int TB = 256;
    const int gN    = (N_NODES + TB - 1) / TB;
    const int gE    = (N_EDGES + TB - 1) / TB;
    const int gGemm = (N_NODES + 127) / 128;   // 782

    static int attr_set = 0;
    if (!attr_set) {
        cudaFuncSetAttribute(k_fused, cudaFuncAttributeMaxDynamicSharedMemorySize, SM_TOT);
        attr_set = 1;
    }

    float* h1p;  cudaGetSymbolAddress((void**)&h1p,  g_h1);
    float* h2p;  cudaGetSymbolAddress((void**)&h2p,  g_h2);
    float* invo; cudaGetSymbolAddress((void**)&invo, g_invo);
    float* invi; cudaGetSymbolAddress((void**)&invi, g_invi);
    float* invu; cudaGetSymbolAddress((void**)&invu, g_invu);
    int* off_in;  cudaGetSymbolAddress((void**)&off_in,  g_off_in);
    int* off_out; cudaGetSymbolAddress((void**)&off_out, g_off_out);
    int* csr_in;  cudaGetSymbolAddress((void**)&csr_in,  g_csr_in);
    int* csr_out; cudaGetSymbolAddress((void**)&csr_out, g_csr_out);
    __nv_bfloat16* wt; cudaGetSymbolAddress((void**)&wt, g_Wt);

    // ---- CSR build ----
    k_zero_cnt<<<gN, TB>>>();
    k_count   <<<gE, TB>>>(src, dst);
    k_scan1   <<<2 * SCAN_NBLK, SCAN_B>>>();
    k_scan3   <<<gN, TB>>>();
    k_fill    <<<gE, TB>>>(src, dst);
    k_prepW   <<<(3 * 8192 + TB - 1) / TB, TB>>>(W1, W2, W3);

    // Layer 1: 'O'  (agg over in-CSR, norm by src out-degree)
    k_fused<<<gGemm, 512, SM_TOT>>>(x, off_in, csr_in, nullptr, nullptr, invo,
                                    wt, b1, h1p, 1);
    // Layer 2: 'I'  (agg over out-CSR, norm by dst in-degree)
    k_fused<<<gGemm, 512, SM_TOT>>>(h1p, off_out, csr_out, nullptr, nullptr, invi,
                                    wt + 2 * 8192, b2, h2p, 1);
    // Layer 3: 'U'  (both CSRs, norm by total degree), no relu
    k_fused<<<gGemm, 512, SM_TOT>>>(h2p, off_in, csr_in, off_out, csr_out, invu,
                                    wt + 4 * 8192, b3, out, 0);
}